// round 14
// baseline (speedup 1.0000x reference)
#include <cuda_runtime.h>
#include <cuda_fp16.h>
#include <stdint.h>

#define NN   20000
#define RR   32
#define EMBD 16
#define HID  128
#define NE   600000
#define NSEG (NN*RR)          // 640000 = 2500 * 256
#define SB   2500             // scan blocks

#define EPB1 1024
#define GRID1 672
#define TLOOP 8
#define GRID_T 768

// ---------------- device scratch ----------------
__device__ int      g_is64;
__device__ int      g_srcA[NE];
__device__ int      g_dstA[NE];
__device__ int      g_relA[NE];
__device__ int      g_seg_cnt[NSEG];
__device__ int      g_seg_ptr[NSEG];
__device__ int      g_seg_cur[NSEG];
__device__ int      g_bsum[SB];
__device__ int      g_boff[SB];
__device__ int      g_rseg_cnt[RR];
__device__ int      g_rseg_ptr[RR + 1];
__device__ int      g_rseg_cur[RR];
__device__ int      g_sdst[NE];         // per active segment: dst node
__device__ int      g_sedge[NE];        // per active segment: first edge slot
__device__ int      g_scnt2[NE];        // per active segment: edge count
__device__ float    g_sinv[NE];         // per active segment: 1/count
__device__ int      g_esrc[NE];         // edges bucketed by segment
__device__ float    g_sx1[NE * EMBD];   // L1 segment rows (inv-scaled sums)
__device__ __half   g_sa2[(size_t)NE * HID];  // L2 segment rows (fp16)
__device__ float    g_h1[NN * HID];
__device__ __half   g_h1f16[NN * HID];
__device__ __half   g_w2hi[(RR + 1) * HID * HID];
__device__ __half   g_w2lo[(RR + 1) * HID * HID];

__device__ __forceinline__ void red_add_v4(float* p, float a, float b, float c, float d) {
    asm volatile("red.global.add.v4.f32 [%0], {%1,%2,%3,%4};"
                 :: "l"(p), "f"(a), "f"(b), "f"(c), "f"(d) : "memory");
}
__device__ __forceinline__ void red_add_v2(float* p, float a, float b) {
    asm volatile("red.global.add.v2.f32 [%0], {%1,%2};"
                 :: "l"(p), "f"(a), "f"(b) : "memory");
}
__device__ __forceinline__ uint32_t smem_u32(const void* p) {
    uint32_t a;
    asm("{ .reg .u64 t; cvta.to.shared.u64 t, %1; cvt.u32.u64 %0, t; }" : "=r"(a) : "l"(p));
    return a;
}
__device__ __forceinline__ void mma_f16(float* c, const uint32_t* a, uint32_t b0, uint32_t b1) {
    asm volatile("mma.sync.aligned.m16n8k16.row.col.f32.f16.f16.f32 "
                 "{%0,%1,%2,%3}, {%4,%5,%6,%7}, {%8,%9}, {%0,%1,%2,%3};"
                 : "+f"(c[0]), "+f"(c[1]), "+f"(c[2]), "+f"(c[3])
                 : "r"(a[0]), "r"(a[1]), "r"(a[2]), "r"(a[3]), "r"(b0), "r"(b1));
}
__device__ __forceinline__ void ldsm_x4(uint32_t* r, uint32_t addr) {
    asm volatile("ldmatrix.sync.aligned.m8n8.x4.shared.b16 {%0,%1,%2,%3}, [%4];"
                 : "=r"(r[0]), "=r"(r[1]), "=r"(r[2]), "=r"(r[3]) : "r"(addr));
}
__device__ __forceinline__ void st_row16(char* tile, int row, int chunk, uint4 v) {
    int byte = row * 256 + chunk * 16;
    byte ^= (byte >> 4) & 0x70;
    *(uint4*)(tile + byte) = v;
}
__device__ __forceinline__ uint32_t frag_addr(uint32_t base, int row0, int kb, int lane) {
    int byte = (row0 + (lane & 15)) * 256 + kb + ((lane >> 4) << 4);
    byte ^= (byte >> 4) & 0x70;
    return base + (uint32_t)byte;
}

// ---------------- preprocessing ----------------
__global__ void k_sniff(const int* ei) {
    __shared__ int ok;
    if (threadIdx.x == 0) ok = 1;
    __syncthreads();
    int hi = ei[2 * threadIdx.x + 1];
    if (hi != 0) atomicExch(&ok, 0);
    __syncthreads();
    if (threadIdx.x == 0) g_is64 = ok;
}

__global__ void k_zero() {
    int i = blockIdx.x * blockDim.x + threadIdx.x;
    if (i < NSEG) g_seg_cnt[i] = 0;
    if (i < RR)   g_rseg_cnt[i] = 0;
}

__global__ void k_decode(const void* ei, const void* et) {
    int e = blockIdx.x * blockDim.x + threadIdx.x;
    if (e >= NE) return;
    if (g_is64) {
        const long long* a = (const long long*)ei;
        const long long* b = (const long long*)et;
        g_srcA[e] = (int)a[e];
        g_dstA[e] = (int)a[NE + e];
        g_relA[e] = (int)b[e];
    } else {
        const int* a = (const int*)ei;
        const int* b = (const int*)et;
        g_srcA[e] = a[e];
        g_dstA[e] = a[NE + e];
        g_relA[e] = b[e];
    }
}

__global__ void k_count() {
    int e = blockIdx.x * blockDim.x + threadIdx.x;
    if (e >= NE) return;
    atomicAdd(&g_seg_cnt[g_relA[e] * NN + g_dstA[e]], 1);
}

// 640k exclusive scan: block sums -> scan sums -> per-element
__global__ void k_scan1() {
    __shared__ int sh[256];
    int i = blockIdx.x * 256 + threadIdx.x;
    sh[threadIdx.x] = (i < NSEG) ? g_seg_cnt[i] : 0;
    __syncthreads();
    for (int off = 128; off > 0; off >>= 1) {
        if (threadIdx.x < off) sh[threadIdx.x] += sh[threadIdx.x + off];
        __syncthreads();
    }
    if (threadIdx.x == 0) g_bsum[blockIdx.x] = sh[0];
}

__global__ void k_scan2() {
    __shared__ int part[256];
    const int t = threadIdx.x;
    const int CH = (SB + 255) / 256;
    int lo = t * CH, hi = min(lo + CH, SB);
    int s = 0;
    for (int i = lo; i < hi; i++) s += g_bsum[i];
    part[t] = s;
    __syncthreads();
    for (int off = 1; off < 256; off <<= 1) {
        int v = (t >= off) ? part[t - off] : 0;
        __syncthreads();
        part[t] += v;
        __syncthreads();
    }
    int run = (t == 0) ? 0 : part[t - 1];
    for (int i = lo; i < hi; i++) {
        g_boff[i] = run;
        run += g_bsum[i];
    }
}

__global__ void k_scan3() {
    __shared__ int sh[256];
    const int t = threadIdx.x;
    int i = blockIdx.x * 256 + t;
    int cnt = (i < NSEG) ? g_seg_cnt[i] : 0;
    sh[t] = cnt;
    __syncthreads();
    for (int off = 1; off < 256; off <<= 1) {
        int v = (t >= off) ? sh[t - off] : 0;
        __syncthreads();
        sh[t] += v;
        __syncthreads();
    }
    if (i < NSEG) {
        int p = g_boff[blockIdx.x] + sh[t] - cnt;
        g_seg_ptr[i] = p;
        g_seg_cur[i] = p;
        if (cnt > 0) atomicAdd(&g_rseg_cnt[i / NN], 1);
    }
}

__global__ void k_rscan() {
    if (threadIdx.x == 0) {
        int a = 0;
        for (int r = 0; r < RR; r++) {
            g_rseg_ptr[r] = a;
            g_rseg_cur[r] = a;
            a += g_rseg_cnt[r];
        }
        g_rseg_ptr[RR] = a;
    }
}

// compact active segments into per-rel contiguous arrays (block-aggregated atomics)
__global__ void k_compact() {
    __shared__ int lcnt[RR], lbase[RR];
    const int t = threadIdx.x;
    if (t < RR) lcnt[t] = 0;
    __syncthreads();
    int i = blockIdx.x * 256 + t;
    int cnt = (i < NSEG) ? g_seg_cnt[i] : 0;
    int r = 0, loc = -1;
    if (cnt > 0) {
        r = i / NN;
        loc = atomicAdd(&lcnt[r], 1);
    }
    __syncthreads();
    if (t < RR && lcnt[t]) lbase[t] = atomicAdd(&g_rseg_cur[t], lcnt[t]);
    __syncthreads();
    if (cnt > 0) {
        int idx = lbase[r] + loc;
        g_sdst[idx]  = i - r * NN;
        g_sedge[idx] = g_seg_ptr[i];
        g_scnt2[idx] = cnt;
        g_sinv[idx]  = 1.0f / (float)cnt;
    }
}

__global__ void k_escatter() {
    int e = blockIdx.x * blockDim.x + threadIdx.x;
    if (e >= NE) return;
    int seg = g_relA[e] * NN + g_dstA[e];
    int slot = atomicAdd(&g_seg_cur[seg], 1);
    g_esrc[slot] = g_srcA[e];
}

__global__ void k_init(const float* __restrict__ b1, const float* __restrict__ b2,
                       float* __restrict__ out) {
    int i = blockIdx.x * blockDim.x + threadIdx.x;
    if (i >= NN * HID) return;
    int h = i & (HID - 1);
    g_h1[i] = b1[h];
    out[i]  = b2[h];
}

__global__ void k_relu_cvt() {
    int i = blockIdx.x * blockDim.x + threadIdx.x;
    if (i >= NN * HID) return;
    g_h1f16[i] = __float2half(fmaxf(g_h1[i], 0.0f));
}

__global__ void k_wcvt(const float* __restrict__ W2, const float* __restrict__ root2) {
    int idx = blockIdx.x * blockDim.x + threadIdx.x;
    if (idx >= (RR + 1) * HID * HID) return;
    int r = idx >> 14, n = (idx >> 7) & 127, k = idx & 127;
    float w = (r < RR) ? W2[((size_t)r * HID + k) * HID + n] : root2[(size_t)k * HID + n];
    __half hi = __float2half(w);
    __half lo = __float2half(w - __half2float(hi));
    g_w2hi[idx] = hi;
    g_w2lo[idx] = lo;
}

// ---------------- segment feature sums ----------------
// L1: g_sx1[row][16] = inv * sum x[src]    (16 lanes per row)
__global__ void __launch_bounds__(256)
k_sum1(const float* __restrict__ X) {
    int row = blockIdx.x * 16 + (threadIdx.x >> 4);
    int lane = threadIdx.x & 15;
    if (row >= g_rseg_ptr[RR]) return;
    int e0 = g_sedge[row], c = g_scnt2[row];
    float a = 0.0f;
    for (int j = 0; j < c; j++)
        a += X[(size_t)g_esrc[e0 + j] * EMBD + lane];
    g_sx1[(size_t)row * EMBD + lane] = a * g_sinv[row];
}

// L2: g_sa2[row][128] = fp16(inv * sum h1[src])   (warp per row, 4 halves/lane)
__global__ void __launch_bounds__(256)
k_sum2() {
    int row = blockIdx.x * 8 + (threadIdx.x >> 5);
    int lane = threadIdx.x & 31;
    if (row >= g_rseg_ptr[RR]) return;
    int e0 = g_sedge[row], c = g_scnt2[row];
    float f0 = 0, f1 = 0, f2 = 0, f3 = 0;
    for (int j = 0; j < c; j++) {
        const __half2* p = (const __half2*)&g_h1f16[(size_t)g_esrc[e0 + j] * HID + lane * 4];
        float2 u = __half22float2(p[0]);
        float2 v = __half22float2(p[1]);
        f0 += u.x; f1 += u.y; f2 += v.x; f3 += v.y;
    }
    float iv = g_sinv[row];
    __half2 h0 = __floats2half2_rn(f0 * iv, f1 * iv);
    __half2 h1 = __floats2half2_rn(f2 * iv, f3 * iv);
    __half2* o = (__half2*)&g_sa2[(size_t)row * HID + lane * 4];
    o[0] = h0; o[1] = h1;
}

// ---------------- layer 1: scalar weight-stationary on segment rows ----------------
__global__ void __launch_bounds__(256)
k_layer1(const float* __restrict__ X, const float* __restrict__ W,
         const float* __restrict__ Wroot) {
    extern __shared__ float sm[];
    float* Ws = sm;
    float* hb = sm + EMBD * HID;

    const int tid  = threadIdx.x;
    const int lane = tid & 31;
    const int warp = tid >> 5;
    const int lane4 = lane * 4;

    int bid = blockIdx.x, acc = 0, rel = -1, chunk = 0, cnt = 0;
    #pragma unroll 1
    for (int r = 0; r <= RR; r++) {
        int c  = (r < RR) ? (g_rseg_ptr[r + 1] - g_rseg_ptr[r]) : NN;
        int nb = (c + EPB1 - 1) / EPB1;
        if (bid < acc + nb) { rel = r; chunk = bid - acc; cnt = c; break; }
        acc += nb;
    }
    if (rel < 0) return;

    const float* Wp = (rel < RR) ? (W + (size_t)rel * EMBD * HID) : Wroot;
    const int base   = (rel < RR) ? g_rseg_ptr[rel] : 0;
    const int cstart = chunk * EPB1;
    const float* XA  = (rel < RR) ? g_sx1 : X;

    for (int i = tid * 4; i < EMBD * HID; i += 256 * 4)
        *(float4*)&Ws[i] = *(const float4*)&Wp[i];
    __syncthreads();

    float* hbw = hb + warp * (8 * EMBD);
    const int ngroups = EPB1 / 8;

    for (int g = warp; g < ngroups; g += 8) {
        int gbase = cstart + g * 8;
        if (gbase >= cnt) break;

        // per-row meta: A row index (contiguous) + dst
        int md = -1;
        if (lane < 8) {
            int gl = gbase + lane;
            if (gl < cnt) md = (rel < RR) ? g_sdst[base + gl] : gl;
        }
        int dsts[8];
        #pragma unroll
        for (int e = 0; e < 8; e++)
            dsts[e] = __shfl_sync(0xffffffffu, md, e);

        __syncwarp();
        if (lane < 16) {
            #pragma unroll
            for (int e = 0; e < 8; e++) {
                int gl = min(gbase + e, cnt - 1);
                int sr = (rel < RR) ? (base + gl) : gl;
                hbw[e * EMBD + lane] = XA[(size_t)sr * EMBD + lane];
            }
        }
        __syncwarp();

        float a0[8], a1[8], a2[8], a3[8];
        #pragma unroll
        for (int e = 0; e < 8; e++) { a0[e] = a1[e] = a2[e] = a3[e] = 0.0f; }

        #pragma unroll 4
        for (int f = 0; f < EMBD; f++) {
            float4 wv = *(float4*)&Ws[f * HID + lane4];
            #pragma unroll
            for (int e = 0; e < 8; e++) {
                float hv = hbw[e * EMBD + f];
                a0[e] += hv * wv.x;
                a1[e] += hv * wv.y;
                a2[e] += hv * wv.z;
                a3[e] += hv * wv.w;
            }
        }

        #pragma unroll
        for (int e = 0; e < 8; e++) {
            if (dsts[e] >= 0) {
                red_add_v4(g_h1 + (size_t)dsts[e] * HID + lane4,
                           a0[e], a1[e], a2[e], a3[e]);
            }
        }
        __syncwarp();
    }
}

// ---------------- layer 2: warp-MMA fp16, W-resident, contiguous segment rows ----------------
#define S_WHI 0
#define S_WLO 32768
#define S_A   65536
#define S_SMEM 98304

__global__ void __launch_bounds__(256)
k_tgemm(float* __restrict__ out) {
    extern __shared__ char smp[];
    const int tid  = threadIdx.x;
    const int wid  = tid >> 5;
    const int lane = tid & 31;
    uint32_t sbase = smem_u32(smp);

    int bid = blockIdx.x, acc = 0, rel = -1, grp = 0, cnt = 0;
    #pragma unroll 1
    for (int r = 0; r <= RR; r++) {
        int c  = (r < RR) ? (g_rseg_ptr[r + 1] - g_rseg_ptr[r]) : NN;
        int nt = (c + 127) >> 7;
        int ng = (nt + TLOOP - 1) / TLOOP;
        if (bid < acc + ng) { rel = r; grp = bid - acc; cnt = c; break; }
        acc += ng;
    }
    if (rel < 0 || cnt == 0) return;

    const int base   = (rel < RR) ? g_rseg_ptr[rel] : 0;
    const int ntile  = (cnt + 127) >> 7;
    const int tstart = grp * TLOOP;
    const int tend   = min(tstart + TLOOP, ntile);
    const __half* XA = (rel < RR) ? g_sa2 : g_h1f16;

    // stage W (hi/lo) once per CTA
    {
        int row = tid >> 1, half = tid & 1;
        const uint4* wh = (const uint4*)&g_w2hi[((size_t)rel * HID + row) * HID];
        const uint4* wl = (const uint4*)&g_w2lo[((size_t)rel * HID + row) * HID];
        #pragma unroll
        for (int j = 0; j < 8; j++) {
            int ch = half * 8 + j;
            st_row16(smp + S_WHI, row, ch, wh[ch]);
            st_row16(smp + S_WLO, row, ch, wl[ch]);
        }
    }

    for (int t = tstart; t < tend; t++) {
        const int tbase = t << 7;
        __syncthreads();

        // stage A rows (contiguous for rel<RR; identity rows for root)
        {
            int row = tid >> 1, half = tid & 1;
            int gl = min(tbase + row, cnt - 1);
            size_t sr = (rel < RR) ? (size_t)(base + gl) : (size_t)gl;
            const uint4* rh = (const uint4*)&XA[sr * HID];
            #pragma unroll
            for (int j = 0; j < 8; j++) {
                int ch = half * 8 + j;
                st_row16(smp + S_A, row, ch, rh[ch]);
            }
        }
        __syncthreads();

        float accm[16][4];
        #pragma unroll
        for (int nt = 0; nt < 16; nt++)
            #pragma unroll
            for (int i = 0; i < 4; i++) accm[nt][i] = 0.0f;

        uint32_t a[4], bh[4], bl[4];
        #pragma unroll 1
        for (int kc = 0; kc < 8; kc++) {
            int kb = kc * 32;
            ldsm_x4(a, frag_addr(sbase + S_A, wid * 16, kb, lane));
            #pragma unroll
            for (int ntp = 0; ntp < 8; ntp++) {
                ldsm_x4(bh, frag_addr(sbase + S_WHI, ntp * 16, kb, lane));
                ldsm_x4(bl, frag_addr(sbase + S_WLO, ntp * 16, kb, lane));
                mma_f16(accm[2 * ntp],     a, bh[0], bh[2]);
                mma_f16(accm[2 * ntp],     a, bl[0], bl[2]);
                mma_f16(accm[2 * ntp + 1], a, bh[1], bh[3]);
                mma_f16(accm[2 * ntp + 1], a, bl[1], bl[3]);
            }
        }

        // epilogue: dst direct; inv already applied in segment rows
        {
            int g = lane >> 2, t4 = lane & 3;
            int r0 = wid * 16 + g, r1 = r0 + 8;
            int gl0 = tbase + r0, gl1 = tbase + r1;
            int d0 = -1, d1 = -1;
            if (gl0 < cnt) d0 = (rel < RR) ? g_sdst[base + gl0] : gl0;
            if (gl1 < cnt) d1 = (rel < RR) ? g_sdst[base + gl1] : gl1;
            float* o0 = out + (size_t)d0 * HID + t4 * 2;
            float* o1 = out + (size_t)d1 * HID + t4 * 2;
            #pragma unroll
            for (int nt = 0; nt < 16; nt++) {
                int off = nt * 8;
                if (d0 >= 0) red_add_v2(o0 + off, accm[nt][0], accm[nt][1]);
                if (d1 >= 0) red_add_v2(o1 + off, accm[nt][2], accm[nt][3]);
            }
        }
    }
}

// ---------------- launch ----------------
extern "C" void kernel_launch(void* const* d_in, const int* in_sizes, int n_in,
                              void* d_out, int out_size) {
    const void*  ei = d_in[0];
    const void*  et = d_in[1];
    const float* x  = (const float*)d_in[2];
    const float* W1 = (const float*)d_in[3];
    const float* r1 = (const float*)d_in[4];
    const float* b1 = (const float*)d_in[5];
    const float* W2 = (const float*)d_in[6];
    const float* r2 = (const float*)d_in[7];
    const float* b2 = (const float*)d_in[8];
    float* out = (float*)d_out;

    const int SM1 = (EMBD * HID + 8 * 8 * EMBD) * 4;   // 12 KB

    static bool attr_done = false;
    if (!attr_done) {
        cudaFuncSetAttribute((const void*)k_tgemm,
                             cudaFuncAttributeMaxDynamicSharedMemorySize, S_SMEM);
        attr_done = true;
    }

    k_sniff   <<<1, 256>>>((const int*)ei);
    k_zero    <<<SB, 256>>>();
    k_decode  <<<(NE + 255) / 256, 256>>>(ei, et);
    k_count   <<<(NE + 255) / 256, 256>>>();
    k_scan1   <<<SB, 256>>>();
    k_scan2   <<<1, 256>>>();
    k_scan3   <<<SB, 256>>>();
    k_rscan   <<<1, 32>>>();
    k_compact <<<SB, 256>>>();
    k_escatter<<<(NE + 255) / 256, 256>>>();
    k_init    <<<(NN * HID + 255) / 256, 256>>>(b1, b2, out);
    k_wcvt    <<<((RR + 1) * HID * HID + 255) / 256, 256>>>(W2, r2);

    // layer 1: segment sums -> scalar GEMM (RED into g_h1, b1-init)
    k_sum1    <<<(NE + 15) / 16, 256>>>(x);
    k_layer1  <<<GRID1, 256, SM1>>>(x, W1, r1);
    k_relu_cvt<<<(NN * HID + 255) / 256, 256>>>();
    // layer 2: segment sums -> fp16 warp-MMA (RED into out, b2-init)
    k_sum2    <<<(NE + 7) / 8, 256>>>();
    k_tgemm   <<<GRID_T, 256, S_SMEM>>>(out);
}

// round 15
// speedup vs baseline: 1.4442x; 1.4442x over previous
#include <cuda_runtime.h>
#include <cuda_fp16.h>
#include <stdint.h>

#define NN   20000
#define RR   32
#define EMBD 16
#define HID  128
#define NE   600000
#define NSEG (NN*RR)

#define TLOOP 8
#define GRID_T 768            // >= sum ceil(ceil(cnt_r/128)/TLOOP) + root groups

// ---------------- device scratch ----------------
__device__ int      g_is64;
__device__ unsigned g_cnt_seg[NSEG];
__device__ int      g_rel_cnt[RR];
__device__ int      g_rel_ptr[RR + 1];
__device__ int      g_rel_cur[RR];
__device__ int      g_srcA[NE];
__device__ int      g_dstA[NE];
__device__ int      g_relA[NE];
__device__ unsigned g_epack[NE];        // rel-sorted: src | dst<<16
__device__ float    g_einv[NE];         // rel-sorted: 1/count(dst,rel)
__device__ float    g_h1[NN * HID];     // fp32 hidden (layer-1 output, b1-init)
__device__ __half   g_xf16[NN * EMBD];  // fp16 input features
__device__ __half   g_h1f16[NN * HID];  // fp16 activations for layer-2 MMA
__device__ __half   g_w1hi[(RR + 1) * HID * EMBD];  // [r][n=128][k=16] (r=32 -> root1)
__device__ __half   g_w1lo[(RR + 1) * HID * EMBD];
__device__ __half   g_w2hi[(RR + 1) * HID * HID];   // [r][n][k] (r=32 -> root2)
__device__ __half   g_w2lo[(RR + 1) * HID * HID];

__device__ __forceinline__ void red_add_v2(float* p, float a, float b) {
    asm volatile("red.global.add.v2.f32 [%0], {%1,%2};"
                 :: "l"(p), "f"(a), "f"(b) : "memory");
}
__device__ __forceinline__ uint32_t smem_u32(const void* p) {
    uint32_t a;
    asm("{ .reg .u64 t; cvta.to.shared.u64 t, %1; cvt.u32.u64 %0, t; }" : "=r"(a) : "l"(p));
    return a;
}

// warp-level fp16 MMA (baseline PTX, sm_80+): D += A(16x16) * B(16x8)
__device__ __forceinline__ void mma_f16(float* c, const uint32_t* a, uint32_t b0, uint32_t b1) {
    asm volatile("mma.sync.aligned.m16n8k16.row.col.f32.f16.f16.f32 "
                 "{%0,%1,%2,%3}, {%4,%5,%6,%7}, {%8,%9}, {%0,%1,%2,%3};"
                 : "+f"(c[0]), "+f"(c[1]), "+f"(c[2]), "+f"(c[3])
                 : "r"(a[0]), "r"(a[1]), "r"(a[2]), "r"(a[3]), "r"(b0), "r"(b1));
}
__device__ __forceinline__ void ldsm_x4(uint32_t* r, uint32_t addr) {
    asm volatile("ldmatrix.sync.aligned.m8n8.x4.shared.b16 {%0,%1,%2,%3}, [%4];"
                 : "=r"(r[0]), "=r"(r[1]), "=r"(r[2]), "=r"(r[3]) : "r"(addr));
}

// layer-2 tiles: 128 rows x 256 bytes; swizzle XORs row low bits into 16B-chunk index
__device__ __forceinline__ void st_row16(char* tile, int row, int chunk, uint4 v) {
    int byte = row * 256 + chunk * 16;
    byte ^= (byte >> 4) & 0x70;
    *(uint4*)(tile + byte) = v;
}
__device__ __forceinline__ uint32_t frag_addr(uint32_t base, int row0, int kb, int lane) {
    int byte = (row0 + (lane & 15)) * 256 + kb + ((lane >> 4) << 4);
    byte ^= (byte >> 4) & 0x70;
    return base + (uint32_t)byte;
}
// layer-1 tiles: 128 rows x 32 bytes (K=16 fp16), linear, no swizzle
__device__ __forceinline__ uint32_t frag_addr16(uint32_t base, int row0, int lane) {
    return base + (uint32_t)((row0 + (lane & 15)) * 32 + ((lane >> 4) << 4));
}

// ---------------- preprocessing ----------------
__global__ void k_sniff(const int* ei) {
    __shared__ int ok;
    if (threadIdx.x == 0) ok = 1;
    __syncthreads();
    int hi = ei[2 * threadIdx.x + 1];
    if (hi != 0) atomicExch(&ok, 0);
    __syncthreads();
    if (threadIdx.x == 0) g_is64 = ok;
}

__global__ void k_zero() {
    int i = blockIdx.x * blockDim.x + threadIdx.x;
    if (i < NSEG) g_cnt_seg[i] = 0u;
    if (i < RR)   g_rel_cnt[i] = 0;
}

__global__ void k_decode(const void* ei, const void* et) {
    int e = blockIdx.x * blockDim.x + threadIdx.x;
    if (e >= NE) return;
    if (g_is64) {
        const long long* a = (const long long*)ei;
        const long long* b = (const long long*)et;
        g_srcA[e] = (int)a[e];
        g_dstA[e] = (int)a[NE + e];
        g_relA[e] = (int)b[e];
    } else {
        const int* a = (const int*)ei;
        const int* b = (const int*)et;
        g_srcA[e] = a[e];
        g_dstA[e] = a[NE + e];
        g_relA[e] = b[e];
    }
}

__global__ void k_count() {
    __shared__ int sh[RR];
    int t = threadIdx.x;
    if (t < RR) sh[t] = 0;
    __syncthreads();
    int e = blockIdx.x * blockDim.x + t;
    if (e < NE) {
        int r = g_relA[e], d = g_dstA[e];
        atomicAdd(&g_cnt_seg[d * RR + r], 1u);
        atomicAdd(&sh[r], 1);
    }
    __syncthreads();
    if (t < RR && sh[t]) atomicAdd(&g_rel_cnt[t], sh[t]);
}

__global__ void k_scan() {
    int acc = 0;
    for (int r = 0; r < RR; r++) {
        g_rel_ptr[r] = acc;
        g_rel_cur[r] = acc;
        acc += g_rel_cnt[r];
    }
    g_rel_ptr[RR] = acc;
}

__global__ void k_scatter() {
    int e = blockIdx.x * blockDim.x + threadIdx.x;
    if (e >= NE) return;
    int r = g_relA[e], s = g_srcA[e], d = g_dstA[e];
    int pos = atomicAdd(&g_rel_cur[r], 1);
    g_epack[pos] = (unsigned)s | ((unsigned)d << 16);
    g_einv[pos]  = 1.0f / (float)g_cnt_seg[d * RR + r];
}

__global__ void k_init(const float* __restrict__ b1, const float* __restrict__ b2,
                       float* __restrict__ out) {
    int i = blockIdx.x * blockDim.x + threadIdx.x;
    if (i >= NN * HID) return;
    int h = i & (HID - 1);
    g_h1[i] = b1[h];
    out[i]  = b2[h];
}

// fp16 convert of input features
__global__ void k_xcvt(const float* __restrict__ x) {
    int i = blockIdx.x * blockDim.x + threadIdx.x;
    if (i < NN * EMBD) g_xf16[i] = __float2half(x[i]);
}

// relu + fp16 convert of h1
__global__ void k_relu_cvt() {
    int i = blockIdx.x * blockDim.x + threadIdx.x;
    if (i >= NN * HID) return;
    g_h1f16[i] = __float2half(fmaxf(g_h1[i], 0.0f));
}

// transpose + fp16-split layer-1 weights: g_w1*[r][n][k] = split(W1[r][k][n])
__global__ void k_w1cvt(const float* __restrict__ W1, const float* __restrict__ root1) {
    int idx = blockIdx.x * blockDim.x + threadIdx.x;
    if (idx >= (RR + 1) * HID * EMBD) return;
    int r = idx >> 11, n = (idx >> 4) & 127, k = idx & 15;
    float w = (r < RR) ? W1[((size_t)r * EMBD + k) * HID + n] : root1[(size_t)k * HID + n];
    __half hi = __float2half(w);
    __half lo = __float2half(w - __half2float(hi));
    g_w1hi[idx] = hi;
    g_w1lo[idx] = lo;
}

// transpose + fp16-split layer-2 weights: g_w2*[((r*128+n)*128)+k] = split(W2[r][k][n])
__global__ void k_wcvt(const float* __restrict__ W2, const float* __restrict__ root2) {
    int idx = blockIdx.x * blockDim.x + threadIdx.x;
    if (idx >= (RR + 1) * HID * HID) return;
    int r = idx >> 14, n = (idx >> 7) & 127, k = idx & 127;
    float w = (r < RR) ? W2[((size_t)r * HID + k) * HID + n] : root2[(size_t)k * HID + n];
    __half hi = __float2half(w);
    __half lo = __float2half(w - __half2float(hi));
    g_w2hi[idx] = hi;
    g_w2lo[idx] = lo;
}

// ---------------- layer 1: fp16 warp-MMA, K=16, W-resident ----------------
// SMEM: W_hi 4K | W_lo 4K | A 4K
#define S1_WHI 0
#define S1_WLO 4096
#define S1_A   8192
#define S1_SMEM 12288

__global__ void __launch_bounds__(256)
k_mma1() {
    extern __shared__ char smp[];
    const int tid  = threadIdx.x;
    const int wid  = tid >> 5;
    const int lane = tid & 31;
    uint32_t sbase = smem_u32(smp);

    int bid = blockIdx.x, acc = 0, rel = -1, grp = 0, cnt = 0;
    #pragma unroll 1
    for (int r = 0; r <= RR; r++) {
        int c  = (r < RR) ? g_rel_cnt[r] : NN;
        int nt = (c + 127) >> 7;
        int ng = (nt + TLOOP - 1) / TLOOP;
        if (bid < acc + ng) { rel = r; grp = bid - acc; cnt = c; break; }
        acc += ng;
    }
    if (rel < 0) return;

    const int base   = (rel < RR) ? g_rel_ptr[rel] : 0;
    const int ntile  = (cnt + 127) >> 7;
    const int tstart = grp * TLOOP;
    const int tend   = min(tstart + TLOOP, ntile);

    // stage W1 (hi/lo) once per CTA: 128 rows x 32B each
    if (tid < 128 * 2) {
        int row = tid >> 1, half = tid & 1;
        const uint4* wh = (const uint4*)&g_w1hi[((size_t)rel * HID + row) * EMBD];
        const uint4* wl = (const uint4*)&g_w1lo[((size_t)rel * HID + row) * EMBD];
        *(uint4*)(smp + S1_WHI + row * 32 + half * 16) = wh[half];
        *(uint4*)(smp + S1_WLO + row * 32 + half * 16) = wl[half];
    }

    for (int t = tstart; t < tend; t++) {
        const int tbase = t << 7;
        __syncthreads();

        // gather A rows (fp16 x, 32B each)
        if (tid < 128 * 2) {
            int row = tid >> 1, half = tid & 1;
            int gl = tbase + row;
            int src = 0;
            if (gl < cnt) src = (rel < RR) ? (int)(g_epack[base + gl] & 0xFFFFu) : gl;
            const uint4* rh = (const uint4*)&g_xf16[(size_t)src * EMBD];
            *(uint4*)(smp + S1_A + row * 32 + half * 16) = rh[half];
        }
        __syncthreads();

        float accm[16][4];
        #pragma unroll
        for (int nt = 0; nt < 16; nt++)
            #pragma unroll
            for (int i = 0; i < 4; i++) accm[nt][i] = 0.0f;

        uint32_t a[4], bh[4], bl[4];
        ldsm_x4(a, frag_addr16(sbase + S1_A, wid * 16, lane));
        #pragma unroll
        for (int ntp = 0; ntp < 8; ntp++) {
            ldsm_x4(bh, frag_addr16(sbase + S1_WHI, ntp * 16, lane));
            ldsm_x4(bl, frag_addr16(sbase + S1_WLO, ntp * 16, lane));
            mma_f16(accm[2 * ntp],     a, bh[0], bh[2]);
            mma_f16(accm[2 * ntp],     a, bl[0], bl[2]);
            mma_f16(accm[2 * ntp + 1], a, bh[1], bh[3]);
            mma_f16(accm[2 * ntp + 1], a, bl[1], bl[3]);
        }

        // epilogue: scaled RED.v2 into g_h1 (b1-init)
        {
            int g = lane >> 2, t4 = lane & 3;
            int r0 = wid * 16 + g, r1 = r0 + 8;
            int gl0 = tbase + r0, gl1 = tbase + r1;
            int d0 = 0, d1 = 0; float iv0 = 0.0f, iv1 = 0.0f;
            if (gl0 < cnt) {
                if (rel < RR) { unsigned pk = g_epack[base + gl0]; d0 = (int)(pk >> 16); iv0 = g_einv[base + gl0]; }
                else          { d0 = gl0; iv0 = 1.0f; }
            }
            if (gl1 < cnt) {
                if (rel < RR) { unsigned pk = g_epack[base + gl1]; d1 = (int)(pk >> 16); iv1 = g_einv[base + gl1]; }
                else          { d1 = gl1; iv1 = 1.0f; }
            }
            float* o0 = g_h1 + (size_t)d0 * HID + t4 * 2;
            float* o1 = g_h1 + (size_t)d1 * HID + t4 * 2;
            #pragma unroll
            for (int nt = 0; nt < 16; nt++) {
                int off = nt * 8;
                if (iv0 > 0.0f) red_add_v2(o0 + off, accm[nt][0] * iv0, accm[nt][1] * iv0);
                if (iv1 > 0.0f) red_add_v2(o1 + off, accm[nt][2] * iv1, accm[nt][3] * iv1);
            }
        }
    }
}

// ---------------- layer 2: warp-MMA fp16 GEMM, W-resident, TLOOP tiles/CTA ----------------
// SMEM: W_hi 32K | W_lo 32K | A 32K   (96 KB -> 2 CTAs/SM)
#define S_WHI 0
#define S_WLO 32768
#define S_A   65536
#define S_SMEM 98304

__global__ void __launch_bounds__(256)
k_tgemm(float* __restrict__ out) {
    extern __shared__ char smp[];
    const int tid  = threadIdx.x;
    const int wid  = tid >> 5;
    const int lane = tid & 31;
    uint32_t sbase = smem_u32(smp);

    int bid = blockIdx.x, acc = 0, rel = -1, grp = 0, cnt = 0;
    #pragma unroll 1
    for (int r = 0; r <= RR; r++) {
        int c  = (r < RR) ? g_rel_cnt[r] : NN;
        int nt = (c + 127) >> 7;
        int ng = (nt + TLOOP - 1) / TLOOP;
        if (bid < acc + ng) { rel = r; grp = bid - acc; cnt = c; break; }
        acc += ng;
    }
    if (rel < 0) return;

    const int base   = (rel < RR) ? g_rel_ptr[rel] : 0;
    const int ntile  = (cnt + 127) >> 7;
    const int tstart = grp * TLOOP;
    const int tend   = min(tstart + TLOOP, ntile);

    // stage W (hi/lo) once per CTA
    {
        int row = tid >> 1, half = tid & 1;
        const uint4* wh = (const uint4*)&g_w2hi[((size_t)rel * HID + row) * HID];
        const uint4* wl = (const uint4*)&g_w2lo[((size_t)rel * HID + row) * HID];
        #pragma unroll
        for (int j = 0; j < 8; j++) {
            int ch = half * 8 + j;
            st_row16(smp + S_WHI, row, ch, wh[ch]);
            st_row16(smp + S_WLO, row, ch, wl[ch]);
        }
    }

    for (int t = tstart; t < tend; t++) {
        const int tbase = t << 7;
        __syncthreads();   // W ready (first iter) / previous MMA+epilogue done

        // gather A rows (fp16) into swizzled tile
        {
            int row = tid >> 1, half = tid & 1;
            int gl = tbase + row;
            int src = 0;
            if (gl < cnt) src = (rel < RR) ? (int)(g_epack[base + gl] & 0xFFFFu) : gl;
            const uint4* rh = (const uint4*)&g_h1f16[(size_t)src * HID];
            #pragma unroll
            for (int j = 0; j < 8; j++) {
                int ch = half * 8 + j;
                st_row16(smp + S_A, row, ch, rh[ch]);
            }
        }
        __syncthreads();

        float accm[16][4];
        #pragma unroll
        for (int nt = 0; nt < 16; nt++)
            #pragma unroll
            for (int i = 0; i < 4; i++) accm[nt][i] = 0.0f;

        uint32_t a[4], bh[4], bl[4];
        #pragma unroll 1
        for (int kc = 0; kc < 8; kc++) {
            int kb = kc * 32;
            ldsm_x4(a, frag_addr(sbase + S_A, wid * 16, kb, lane));
            #pragma unroll
            for (int ntp = 0; ntp < 8; ntp++) {
                ldsm_x4(bh, frag_addr(sbase + S_WHI, ntp * 16, kb, lane));
                ldsm_x4(bl, frag_addr(sbase + S_WLO, ntp * 16, kb, lane));
                mma_f16(accm[2 * ntp],     a, bh[0], bh[2]);
                mma_f16(accm[2 * ntp],     a, bl[0], bl[2]);
                mma_f16(accm[2 * ntp + 1], a, bh[1], bh[3]);
                mma_f16(accm[2 * ntp + 1], a, bl[1], bl[3]);
            }
        }

        // epilogue: meta direct from gmem; scaled RED.v2 into out
        {
            int g = lane >> 2, t4 = lane & 3;
            int r0 = wid * 16 + g, r1 = r0 + 8;
            int gl0 = tbase + r0, gl1 = tbase + r1;
            int d0 = 0, d1 = 0; float iv0 = 0.0f, iv1 = 0.0f;
            if (gl0 < cnt) {
                if (rel < RR) { unsigned pk = g_epack[base + gl0]; d0 = (int)(pk >> 16); iv0 = g_einv[base + gl0]; }
                else          { d0 = gl0; iv0 = 1.0f; }
            }
            if (gl1 < cnt) {
                if (rel < RR) { unsigned pk = g_epack[base + gl1]; d1 = (int)(pk >> 16); iv1 = g_einv[base + gl1]; }
                else          { d1 = gl1; iv1 = 1.0f; }
            }
            float* o0 = out + (size_t)d0 * HID + t4 * 2;
            float* o1 = out + (size_t)d1 * HID + t4 * 2;
            #pragma unroll
            for (int nt = 0; nt < 16; nt++) {
                int off = nt * 8;
                if (iv0 > 0.0f) red_add_v2(o0 + off, accm[nt][0] * iv0, accm[nt][1] * iv0);
                if (iv1 > 0.0f) red_add_v2(o1 + off, accm[nt][2] * iv1, accm[nt][3] * iv1);
            }
        }
    }
}

// ---------------- launch ----------------
extern "C" void kernel_launch(void* const* d_in, const int* in_sizes, int n_in,
                              void* d_out, int out_size) {
    const void*  ei = d_in[0];
    const void*  et = d_in[1];
    const float* x  = (const float*)d_in[2];
    const float* W1 = (const float*)d_in[3];
    const float* r1 = (const float*)d_in[4];
    const float* b1 = (const float*)d_in[5];
    const float* W2 = (const float*)d_in[6];
    const float* r2 = (const float*)d_in[7];
    const float* b2 = (const float*)d_in[8];
    float* out = (float*)d_out;

    static bool attr_done = false;
    if (!attr_done) {
        cudaFuncSetAttribute((const void*)k_tgemm,
                             cudaFuncAttributeMaxDynamicSharedMemorySize, S_SMEM);
        attr_done = true;
    }

    k_sniff  <<<1, 256>>>((const int*)ei);
    k_zero   <<<(NSEG + 255) / 256, 256>>>();
    k_decode <<<(NE + 255) / 256, 256>>>(ei, et);
    k_count  <<<(NE + 255) / 256, 256>>>();
    k_scan   <<<1, 1>>>();
    k_scatter<<<(NE + 255) / 256, 256>>>();
    k_init   <<<(NN * HID + 255) / 256, 256>>>(b1, b2, out);
    k_xcvt   <<<(NN * EMBD + 255) / 256, 256>>>(x);
    k_w1cvt  <<<((RR + 1) * HID * EMBD + 255) / 256, 256>>>(W1, r1);
    k_wcvt   <<<((RR + 1) * HID * HID + 255) / 256, 256>>>(W2, r2);

    // layer 1: fp16 warp-MMA (K=16), RED into g_h1 (b1-initialized)
    k_mma1   <<<GRID_T, 256, S1_SMEM>>>();
    k_relu_cvt<<<(NN * HID + 255) / 256, 256>>>();
    // layer 2: fp16 warp-MMA, W-resident, RED into out (b2-initialized)
    k_tgemm  <<<GRID_T, 256, S_SMEM>>>(out);
}